// round 15
// baseline (speedup 1.0000x reference)
#include <cuda_runtime.h>
#include <cuda_bf16.h>
#include <cstdint>
#include <cmath>

#define NG    8192
#define BGRP  16
#define GS    512
#define DIM   768

// tile sizes (proven config)
#define TBM 128
#define TBN 128
#define TBK 64
#define NSTAGE 3
#define STAGE_ELEMS (TBM * TBK)                   // 8192 bf16 per operand per stage
#define SMEM_BYTES (NSTAGE * 2 * STAGE_ELEMS * 2) // 98304 bytes

#define SCALE_CONST 0.03608439182435161f          // 1/sqrt(768)

#if defined(__CUDA_ARCH__) && __CUDA_ARCH__ >= 900
#define GRID_DEP_SYNC() cudaGridDependencySynchronize()
#else
#define GRID_DEP_SYNC()
#endif

// ---------------- scratch (device globals; no allocs allowed) ----------------
__device__ __nv_bfloat16 g_xb [NG * DIM];
__device__ __nv_bfloat16 g_Wqb[DIM * DIM];
__device__ __nv_bfloat16 g_Wkb[DIM * DIM];
__device__ __nv_bfloat16 g_Wvb[DIM * DIM];
__device__ __nv_bfloat16 g_Wob[DIM * DIM];
__device__ __nv_bfloat16 g_Q  [NG * DIM];
__device__ __nv_bfloat16 g_K  [NG * DIM];
__device__ __nv_bfloat16 g_V  [NG * DIM];
__device__ __nv_bfloat16 g_P  [BGRP * GS * GS];   // unnormalized exp-scores, bf16
__device__ float         g_rs [NG];               // per-row exp sums
__device__ __nv_bfloat16 g_DYN[NG * DIM];

// ---------------- helpers ----------------
__device__ __forceinline__ unsigned sptr(const void* p) {
    return (unsigned)__cvta_generic_to_shared(p);
}
__device__ __forceinline__ void cpasync16(unsigned s, const void* g) {
    asm volatile("cp.async.cg.shared.global [%0], [%1], 16;\n" :: "r"(s), "l"(g));
}
__device__ __forceinline__ void cp_commit() {
    asm volatile("cp.async.commit_group;\n" ::: "memory");
}
__device__ __forceinline__ void cp_wait1() {
    asm volatile("cp.async.wait_group 1;\n" ::: "memory");
}
__device__ __forceinline__ void ldsm4(unsigned& r0, unsigned& r1, unsigned& r2, unsigned& r3, unsigned a) {
    asm volatile("ldmatrix.sync.aligned.m8n8.x4.shared.b16 {%0,%1,%2,%3}, [%4];\n"
                 : "=r"(r0), "=r"(r1), "=r"(r2), "=r"(r3) : "r"(a));
}
__device__ __forceinline__ void ldsm4t(unsigned& r0, unsigned& r1, unsigned& r2, unsigned& r3, unsigned a) {
    asm volatile("ldmatrix.sync.aligned.m8n8.x4.trans.shared.b16 {%0,%1,%2,%3}, [%4];\n"
                 : "=r"(r0), "=r"(r1), "=r"(r2), "=r"(r3) : "r"(a));
}
__device__ __forceinline__ void mma16816(float* d, const unsigned* a, const unsigned* b) {
    asm volatile(
        "mma.sync.aligned.m16n8k16.row.col.f32.bf16.bf16.f32 "
        "{%0,%1,%2,%3}, {%4,%5,%6,%7}, {%8,%9}, {%0,%1,%2,%3};\n"
        : "+f"(d[0]), "+f"(d[1]), "+f"(d[2]), "+f"(d[3])
        : "r"(a[0]), "r"(a[1]), "r"(a[2]), "r"(a[3]), "r"(b[0]), "r"(b[1]));
}

// ---- cp.async tile issue into stage buffers (BK=64 -> 128B rows, 8-way XOR swizzle) ----
template<bool TB>
__device__ __forceinline__ void issue_tile(
    const __nv_bfloat16* __restrict__ A, const __nv_bfloat16* __restrict__ B,
    __nv_bfloat16* As, __nv_bfloat16* Bs,
    int row0, int col0, int lda, int ldb, int kt, int tid)
{
#pragma unroll
    for (int i = 0; i < 4; i++) {
        int lin = tid + i * 256;
        int r = lin >> 3, c = lin & 7;
        const __nv_bfloat16* g = A + (long)(row0 + r) * lda + kt * TBK + c * 8;
        cpasync16(sptr(As + r * TBK + ((c ^ (r & 7)) << 3)), g);
    }
    if (!TB) {
#pragma unroll
        for (int i = 0; i < 4; i++) {
            int lin = tid + i * 256;
            int r = lin >> 3, c = lin & 7;
            const __nv_bfloat16* g = B + (long)(col0 + r) * ldb + kt * TBK + c * 8;
            cpasync16(sptr(Bs + r * TBK + ((c ^ (r & 7)) << 3)), g);
        }
    } else {
#pragma unroll
        for (int i = 0; i < 4; i++) {
            int lin = tid + i * 256;
            int r = lin >> 4, c = lin & 15;
            const __nv_bfloat16* g = B + (long)(kt * TBK + r) * ldb + col0 + c * 8;
            cpasync16(sptr(Bs + r * TBN + ((c ^ (r & 7)) << 3)), g);
        }
    }
}

// ---------------------------------------------------------------------------
// Core bf16 tensor-core GEMM body (single-barrier 3-stage pipeline, prefetch
// hoisted BEFORE compute: wait -> sync -> issue(kt+2) -> commit -> compute(kt);
// buffer (kt+2)%3 == (kt-1)%3 is free once the barrier passes).
// MODE 0: bf16 C = acc + bias[col]                      (QKV projections)
// MODE 1: bf16 C = exp(acc*scale) diag-masked; row sums atomically added to
//         rowsum (= bias ptr, non-const)                (fused scores+exp)
// MODE 2: bf16 C = acc * (1/rowsum[row])  (rowsum = bias ptr)   (PV + norm)
// MODE 3: fp32 C = X + beta[0]*(acc + bias[col])        (out-proj + residual)
// ---------------------------------------------------------------------------
template<int MODE, bool TB>
__device__ __forceinline__ void gemm_body(
    const __nv_bfloat16* __restrict__ A, const __nv_bfloat16* __restrict__ B,
    const float* __restrict__ bias, void* __restrict__ Cv,
    int K, int lda, int ldb, int ldc,
    const float* __restrict__ X, const float* __restrict__ beta,
    char* dsm, int row0, int col0)
{
    __nv_bfloat16* As = reinterpret_cast<__nv_bfloat16*>(dsm);
    __nv_bfloat16* Bs = As + NSTAGE * STAGE_ELEMS;

    const int tid  = threadIdx.x;
    const int lane = tid & 31;
    const int wid  = tid >> 5;
    const int wm   = (wid & 1) * 64;
    const int wn   = (wid >> 1) * 32;

    float acc[4][4][4];
#pragma unroll
    for (int i = 0; i < 4; i++)
#pragma unroll
        for (int j = 0; j < 4; j++)
#pragma unroll
            for (int k = 0; k < 4; k++) acc[i][j][k] = 0.f;

    const int ntiles = K / TBK;

    GRID_DEP_SYNC();

    issue_tile<TB>(A, B, As, Bs, row0, col0, lda, ldb, 0, tid);
    cp_commit();
    issue_tile<TB>(A, B, As + STAGE_ELEMS, Bs + STAGE_ELEMS, row0, col0, lda, ldb, 1, tid);
    cp_commit();

    for (int kt = 0; kt < ntiles; kt++) {
        const int stg = kt % NSTAGE;
        cp_wait1();              // tile kt resident (<=1 pending group)
        __syncthreads();         // all threads done with buffer (kt-1)%3

        // hoisted prefetch: issue kt+2 into the just-freed buffer BEFORE compute
        if (kt + 2 < ntiles) {
            const int ps = (kt + 2) % NSTAGE;
            issue_tile<TB>(A, B, As + ps * STAGE_ELEMS, Bs + ps * STAGE_ELEMS,
                           row0, col0, lda, ldb, kt + 2, tid);
        }
        cp_commit();

        const __nv_bfloat16* Asb = As + stg * STAGE_ELEMS;
        const __nv_bfloat16* Bsb = Bs + stg * STAGE_ELEMS;

#pragma unroll
        for (int ks = 0; ks < 4; ks++) {
            unsigned aF[4][4], bF[4][2];
#pragma unroll
            for (int mi = 0; mi < 4; mi++) {
                int r = wm + mi * 16 + (lane & 15);
                int c = ks * 2 + (lane >> 4);
                ldsm4(aF[mi][0], aF[mi][1], aF[mi][2], aF[mi][3],
                      sptr(Asb + r * TBK + ((c ^ (r & 7)) << 3)));
            }
            if (!TB) {
#pragma unroll
                for (int nt = 0; nt < 2; nt++) {
                    int r = wn + nt * 16 + (lane & 15);
                    int c = ks * 2 + (lane >> 4);
                    unsigned r0, r1, r2, r3;
                    ldsm4(r0, r1, r2, r3,
                          sptr(Bsb + r * TBK + ((c ^ (r & 7)) << 3)));
                    bF[nt * 2 + 0][0] = r0; bF[nt * 2 + 0][1] = r2;
                    bF[nt * 2 + 1][0] = r1; bF[nt * 2 + 1][1] = r3;
                }
            } else {
#pragma unroll
                for (int nt = 0; nt < 2; nt++) {
                    int r = ks * 16 + (lane & 15);
                    int c = (wn >> 3) + nt * 2 + (lane >> 4);
                    unsigned r0, r1, r2, r3;
                    ldsm4t(r0, r1, r2, r3,
                           sptr(Bsb + r * TBN + ((c ^ (r & 7)) << 3)));
                    bF[nt * 2 + 0][0] = r0; bF[nt * 2 + 0][1] = r1;
                    bF[nt * 2 + 1][0] = r2; bF[nt * 2 + 1][1] = r3;
                }
            }
#pragma unroll
            for (int mi = 0; mi < 4; mi++)
#pragma unroll
                for (int nj = 0; nj < 4; nj++)
                    mma16816(acc[mi][nj], aF[mi], bF[nj]);
        }
    }

    // ---------------- epilogue ----------------
    const int rg = lane >> 2;
    const int t  = lane & 3;
    float betav = 0.f;
    if (MODE == 3) betav = beta[0];

    float rsum[4][2];
    if (MODE == 1) {
#pragma unroll
        for (int i = 0; i < 4; i++) { rsum[i][0] = 0.f; rsum[i][1] = 0.f; }
    }

#pragma unroll
    for (int mi = 0; mi < 4; mi++) {
        float inv0 = 0.f, inv1 = 0.f;
        if (MODE == 2) {
            const int r = row0 + wm + mi * 16 + rg;
            inv0 = 1.f / bias[r];
            inv1 = 1.f / bias[r + 8];
        }
#pragma unroll
        for (int nj = 0; nj < 4; nj++) {
            const int r = row0 + wm + mi * 16 + rg;
            const int c = col0 + wn + nj * 8 + t * 2;
            const float d0 = acc[mi][nj][0];
            const float d1 = acc[mi][nj][1];
            const float d2 = acc[mi][nj][2];
            const float d3 = acc[mi][nj][3];

            if (MODE == 0) {
                __nv_bfloat16* C = reinterpret_cast<__nv_bfloat16*>(Cv);
                const float2 bb = *reinterpret_cast<const float2*>(bias + c);
                *reinterpret_cast<__nv_bfloat162*>(C + (long)r * ldc + c) =
                    __floats2bfloat162_rn(d0 + bb.x, d1 + bb.y);
                *reinterpret_cast<__nv_bfloat162*>(C + (long)(r + 8) * ldc + c) =
                    __floats2bfloat162_rn(d2 + bb.x, d3 + bb.y);
            } else if (MODE == 1) {
                __nv_bfloat16* C = reinterpret_cast<__nv_bfloat16*>(Cv);
                float e0 = (r     == c    ) ? 0.f : __expf(d0 * SCALE_CONST);
                float e1 = (r     == c + 1) ? 0.f : __expf(d1 * SCALE_CONST);
                float e2 = (r + 8 == c    ) ? 0.f : __expf(d2 * SCALE_CONST);
                float e3 = (r + 8 == c + 1) ? 0.f : __expf(d3 * SCALE_CONST);
                *reinterpret_cast<__nv_bfloat162*>(C + (long)r * ldc + c) =
                    __floats2bfloat162_rn(e0, e1);
                *reinterpret_cast<__nv_bfloat162*>(C + (long)(r + 8) * ldc + c) =
                    __floats2bfloat162_rn(e2, e3);
                rsum[mi][0] += e0 + e1;
                rsum[mi][1] += e2 + e3;
            } else if (MODE == 2) {
                __nv_bfloat16* C = reinterpret_cast<__nv_bfloat16*>(Cv);
                *reinterpret_cast<__nv_bfloat162*>(C + (long)r * ldc + c) =
                    __floats2bfloat162_rn(d0 * inv0, d1 * inv0);
                *reinterpret_cast<__nv_bfloat162*>(C + (long)(r + 8) * ldc + c) =
                    __floats2bfloat162_rn(d2 * inv1, d3 * inv1);
            } else {
                float* C = reinterpret_cast<float*>(Cv);
                const float2 bb = *reinterpret_cast<const float2*>(bias + c);
                const float2 x0 = *reinterpret_cast<const float2*>(X + (long)r * ldc + c);
                const float2 x1 = *reinterpret_cast<const float2*>(X + (long)(r + 8) * ldc + c);
                *reinterpret_cast<float2*>(C + (long)r * ldc + c) =
                    make_float2(x0.x + betav * (d0 + bb.x), x0.y + betav * (d1 + bb.y));
                *reinterpret_cast<float2*>(C + (long)(r + 8) * ldc + c) =
                    make_float2(x1.x + betav * (d2 + bb.x), x1.y + betav * (d3 + bb.y));
            }
        }
    }

    if (MODE == 1) {
        float* rs = const_cast<float*>(bias);
#pragma unroll
        for (int mi = 0; mi < 4; mi++) {
            float s0 = rsum[mi][0], s1 = rsum[mi][1];
            s0 += __shfl_xor_sync(0xffffffffu, s0, 1);
            s0 += __shfl_xor_sync(0xffffffffu, s0, 2);
            s1 += __shfl_xor_sync(0xffffffffu, s1, 1);
            s1 += __shfl_xor_sync(0xffffffffu, s1, 2);
            if (t == 0) {
                const int r = row0 + wm + mi * 16 + rg;
                atomicAdd(rs + r, s0);
                atomicAdd(rs + r + 8, s1);
            }
        }
    }
}

// ---------------- QKV fused: grid.z in {0,1,2} selects W/bias/C ----------------
__global__ __launch_bounds__(256, 2)
void hgemm_qkv(const __nv_bfloat16* __restrict__ A,
               const __nv_bfloat16* __restrict__ W0, const __nv_bfloat16* __restrict__ W1,
               const __nv_bfloat16* __restrict__ W2,
               const float* __restrict__ b0, const float* __restrict__ b1,
               const float* __restrict__ b2,
               __nv_bfloat16* __restrict__ C0, __nv_bfloat16* __restrict__ C1,
               __nv_bfloat16* __restrict__ C2)
{
    extern __shared__ char dsm[];
    const int z = blockIdx.z;
    const __nv_bfloat16* W = (z == 0) ? W0 : (z == 1) ? W1 : W2;
    const float* bias      = (z == 0) ? b0 : (z == 1) ? b1 : b2;
    __nv_bfloat16* C       = (z == 0) ? C0 : (z == 1) ? C1 : C2;
    gemm_body<0, false>(A, W, bias, C, DIM, DIM, DIM, DIM, nullptr, nullptr,
                        dsm, blockIdx.y * TBM, blockIdx.x * TBN);
}

// ---------------- generic batched GEMM (z = group) ----------------
template<int MODE, bool TB>
__global__ __launch_bounds__(256, 2)
void hgemm(const __nv_bfloat16* __restrict__ A, const __nv_bfloat16* __restrict__ B,
           const float* __restrict__ bias, void* __restrict__ Cv,
           int K, int lda, int ldb, int ldc,
           long sA, long sB, long sC,
           const float* __restrict__ X, const float* __restrict__ beta)
{
    extern __shared__ char dsm[];
    const int bz = blockIdx.z;
    void* C;
    if (MODE == 3) C = (void*)((float*)Cv + bz * sC);
    else           C = (void*)((__nv_bfloat16*)Cv + bz * sC);
    const float* b = (MODE == 1 || MODE == 2) ? bias + (long)bz * GS : bias;
    gemm_body<MODE, TB>(A + bz * sA, B + bz * sB, b, C,
                        K, lda, ldb, ldc, X, beta,
                        dsm, blockIdx.y * TBM, blockIdx.x * TBN);
}

// ---------------- merged fp32 -> bf16 converts + rowsum zeroing ----------------
__global__ __launch_bounds__(256)
void conv_all(const float* __restrict__ x,
              const float* __restrict__ wq, const float* __restrict__ wk,
              const float* __restrict__ wv, const float* __restrict__ wo,
              __nv_bfloat16* __restrict__ xb,
              __nv_bfloat16* __restrict__ wqb, __nv_bfloat16* __restrict__ wkb,
              __nv_bfloat16* __restrict__ wvb, __nv_bfloat16* __restrict__ wob,
              float* __restrict__ rowsum)
{
    GRID_DEP_SYNC();
    long gid = (long)blockIdx.x * 256 + threadIdx.x;
    if (gid < NG) rowsum[gid] = 0.f;

    const long NX = (long)NG * DIM;
    const long W  = (long)DIM * DIM;
    long i = gid * 4;
    if (i >= NX + 4 * W) return;
    const float* src;
    __nv_bfloat16* dst;
    long off;
    if (i < NX) { src = x; dst = xb; off = i; }
    else {
        long j = i - NX;
        int w = (int)(j / W);
        off = j - (long)w * W;
        src = (w == 0) ? wq : (w == 1) ? wk : (w == 2) ? wv : wo;
        dst = (w == 0) ? wqb : (w == 1) ? wkb : (w == 2) ? wvb : wob;
    }
    float4 v = *reinterpret_cast<const float4*>(src + off);
    *reinterpret_cast<__nv_bfloat162*>(dst + off)     = __floats2bfloat162_rn(v.x, v.y);
    *reinterpret_cast<__nv_bfloat162*>(dst + off + 2) = __floats2bfloat162_rn(v.z, v.w);
}

// ---------------------------------------------------------------------------
// Launcher. Inputs: x, batch(unused), Wq,bq, Wk,bk, Wv,bv, Wo,bo, beta.
// 5 kernels, all PDL-linked:
//   conv_all -> QKV -> scores(exp+rowsum) -> PV(normalize) -> out-proj
// ---------------------------------------------------------------------------
extern "C" void kernel_launch(void* const* d_in, const int* in_sizes, int n_in,
                              void* d_out, int out_size)
{
    (void)in_sizes; (void)n_in; (void)out_size;
    const float* x    = (const float*)d_in[0];
    const float* Wq   = (const float*)d_in[2];
    const float* bq   = (const float*)d_in[3];
    const float* Wk   = (const float*)d_in[4];
    const float* bk   = (const float*)d_in[5];
    const float* Wv   = (const float*)d_in[6];
    const float* bv   = (const float*)d_in[7];
    const float* Wo   = (const float*)d_in[8];
    const float* bo   = (const float*)d_in[9];
    const float* beta = (const float*)d_in[10];
    float* out = (float*)d_out;

    __nv_bfloat16 *xb, *Wqb, *Wkb, *Wvb, *Wob, *Q, *K, *V, *P, *DYN;
    float *RS;
    cudaGetSymbolAddress((void**)&xb,  g_xb);
    cudaGetSymbolAddress((void**)&Wqb, g_Wqb);
    cudaGetSymbolAddress((void**)&Wkb, g_Wkb);
    cudaGetSymbolAddress((void**)&Wvb, g_Wvb);
    cudaGetSymbolAddress((void**)&Wob, g_Wob);
    cudaGetSymbolAddress((void**)&Q,   g_Q);
    cudaGetSymbolAddress((void**)&K,   g_K);
    cudaGetSymbolAddress((void**)&V,   g_V);
    cudaGetSymbolAddress((void**)&P,   g_P);
    cudaGetSymbolAddress((void**)&RS,  g_rs);
    cudaGetSymbolAddress((void**)&DYN, g_DYN);

    static bool init_done = false;
    if (!init_done) {
        cudaFuncSetAttribute(hgemm_qkv,       cudaFuncAttributeMaxDynamicSharedMemorySize, SMEM_BYTES);
        cudaFuncSetAttribute(hgemm<1, false>, cudaFuncAttributeMaxDynamicSharedMemorySize, SMEM_BYTES);
        cudaFuncSetAttribute(hgemm<2, true>,  cudaFuncAttributeMaxDynamicSharedMemorySize, SMEM_BYTES);
        cudaFuncSetAttribute(hgemm<3, false>, cudaFuncAttributeMaxDynamicSharedMemorySize, SMEM_BYTES);
        init_done = true;
    }

    cudaLaunchAttribute pdl[1];
    pdl[0].id = cudaLaunchAttributeProgrammaticStreamSerialization;
    pdl[0].val.programmaticStreamSerializationAllowed = 1;

    auto mkcfg = [&](dim3 g, dim3 b, size_t sm) {
        cudaLaunchConfig_t cfg{};
        cfg.gridDim = g;
        cfg.blockDim = b;
        cfg.dynamicSmemBytes = sm;
        cfg.stream = 0;
        cfg.attrs = pdl;
        cfg.numAttrs = 1;
        return cfg;
    };

    // converts + rowsum zero (one launch)
    {
        long total4 = ((long)NG * DIM + 4L * DIM * DIM) / 4;
        int blocks = (int)((total4 + 255) / 256);
        cudaLaunchConfig_t cfg = mkcfg(dim3(blocks), dim3(256), 0);
        cudaLaunchKernelEx(&cfg, conv_all, x, Wq, Wk, Wv, Wo,
                           xb, Wqb, Wkb, Wvb, Wob, RS);
    }

    // Q/K/V projections in one launch
    {
        cudaLaunchConfig_t cfg = mkcfg(dim3(6, 64, 3), dim3(256), SMEM_BYTES);
        cudaLaunchKernelEx(&cfg, hgemm_qkv, (const __nv_bfloat16*)xb,
                           (const __nv_bfloat16*)Wqb, (const __nv_bfloat16*)Wkb,
                           (const __nv_bfloat16*)Wvb, bq, bk, bv, Q, K, V);
    }

    // fused scores+exp+rowsum: P_g = exp(scale * Q_g K_g^T) masked, bf16
    {
        cudaLaunchConfig_t cfg = mkcfg(dim3(4, 4, BGRP), dim3(256), SMEM_BYTES);
        cudaLaunchKernelEx(&cfg, hgemm<1, false>,
                           (const __nv_bfloat16*)Q, (const __nv_bfloat16*)K,
                           (const float*)RS, (void*)P,
                           DIM, DIM, DIM, GS,
                           (long)GS * DIM, (long)GS * DIM, (long)GS * GS,
                           (const float*)nullptr, (const float*)nullptr);
    }

    // PV + normalization: DYN_g = (P_g @ V_g) / rowsum
    {
        cudaLaunchConfig_t cfg = mkcfg(dim3(6, 4, BGRP), dim3(256), SMEM_BYTES);
        cudaLaunchKernelEx(&cfg, hgemm<2, true>,
                           (const __nv_bfloat16*)P, (const __nv_bfloat16*)V,
                           (const float*)RS, (void*)DYN,
                           GS, GS, DIM, DIM,
                           (long)GS * GS, (long)GS * DIM, (long)GS * DIM,
                           (const float*)nullptr, (const float*)nullptr);
    }

    // out = x + beta*(DYN @ Wo^T + bo)
    {
        cudaLaunchConfig_t cfg = mkcfg(dim3(6, 64, 1), dim3(256), SMEM_BYTES);
        cudaLaunchKernelEx(&cfg, hgemm<3, false>,
                           (const __nv_bfloat16*)DYN, (const __nv_bfloat16*)Wob,
                           bo, (void*)out,
                           DIM, DIM, DIM, DIM, 0L, 0L, 0L,
                           x, beta);
    }
}

// round 16
// speedup vs baseline: 1.1101x; 1.1101x over previous
#include <cuda_runtime.h>
#include <cuda_bf16.h>
#include <cstdint>
#include <cmath>

#define NG    8192
#define BGRP  16
#define GS    512
#define DIM   768

// tile sizes (proven config)
#define TBM 128
#define TBN 128
#define TBK 64
#define NSTAGE 3
#define STAGE_ELEMS (TBM * TBK)                   // 8192 bf16 per operand per stage
#define SMEM_BYTES (NSTAGE * 2 * STAGE_ELEMS * 2) // 98304 bytes

#define SCALE_CONST 0.03608439182435161f          // 1/sqrt(768)

#if defined(__CUDA_ARCH__) && __CUDA_ARCH__ >= 900
#define GRID_DEP_SYNC() cudaGridDependencySynchronize()
#else
#define GRID_DEP_SYNC()
#endif

// ---------------- scratch (device globals; no allocs allowed) ----------------
__device__ __nv_bfloat16 g_xb  [NG * DIM];
__device__ __nv_bfloat16 g_Wqb [DIM * DIM];
__device__ __nv_bfloat16 g_Wkb [DIM * DIM];
__device__ __nv_bfloat16 g_Wvb [DIM * DIM];
__device__ __nv_bfloat16 g_Wob [DIM * DIM];
__device__ __nv_bfloat16 g_Wvo [DIM * DIM];       // combined Wo@Wv, bf16
__device__ float         g_bvo [DIM];             // Wo@bv
__device__ __nv_bfloat16 g_Q   [NG * DIM];
__device__ __nv_bfloat16 g_K   [NG * DIM];
__device__ __nv_bfloat16 g_VW  [NG * DIM];        // x@Wvo^T + bvo
__device__ __nv_bfloat16 g_P   [BGRP * GS * GS];  // unnormalized exp-scores
__device__ float         g_rs  [NG];              // per-row exp sums

// ---------------- helpers ----------------
__device__ __forceinline__ unsigned sptr(const void* p) {
    return (unsigned)__cvta_generic_to_shared(p);
}
__device__ __forceinline__ void cpasync16(unsigned s, const void* g) {
    asm volatile("cp.async.cg.shared.global [%0], [%1], 16;\n" :: "r"(s), "l"(g));
}
__device__ __forceinline__ void cp_commit() {
    asm volatile("cp.async.commit_group;\n" ::: "memory");
}
__device__ __forceinline__ void cp_wait1() {
    asm volatile("cp.async.wait_group 1;\n" ::: "memory");
}
__device__ __forceinline__ void ldsm4(unsigned& r0, unsigned& r1, unsigned& r2, unsigned& r3, unsigned a) {
    asm volatile("ldmatrix.sync.aligned.m8n8.x4.shared.b16 {%0,%1,%2,%3}, [%4];\n"
                 : "=r"(r0), "=r"(r1), "=r"(r2), "=r"(r3) : "r"(a));
}
__device__ __forceinline__ void ldsm4t(unsigned& r0, unsigned& r1, unsigned& r2, unsigned& r3, unsigned a) {
    asm volatile("ldmatrix.sync.aligned.m8n8.x4.trans.shared.b16 {%0,%1,%2,%3}, [%4];\n"
                 : "=r"(r0), "=r"(r1), "=r"(r2), "=r"(r3) : "r"(a));
}
__device__ __forceinline__ void mma16816(float* d, const unsigned* a, const unsigned* b) {
    asm volatile(
        "mma.sync.aligned.m16n8k16.row.col.f32.bf16.bf16.f32 "
        "{%0,%1,%2,%3}, {%4,%5,%6,%7}, {%8,%9}, {%0,%1,%2,%3};\n"
        : "+f"(d[0]), "+f"(d[1]), "+f"(d[2]), "+f"(d[3])
        : "r"(a[0]), "r"(a[1]), "r"(a[2]), "r"(a[3]), "r"(b[0]), "r"(b[1]));
}

// ---- cp.async tile issue into stage buffers (BK=64 -> 128B rows, 8-way XOR swizzle) ----
template<bool TB>
__device__ __forceinline__ void issue_tile(
    const __nv_bfloat16* __restrict__ A, const __nv_bfloat16* __restrict__ B,
    __nv_bfloat16* As, __nv_bfloat16* Bs,
    int row0, int col0, int lda, int ldb, int kt, int tid)
{
#pragma unroll
    for (int i = 0; i < 4; i++) {
        int lin = tid + i * 256;
        int r = lin >> 3, c = lin & 7;
        const __nv_bfloat16* g = A + (long)(row0 + r) * lda + kt * TBK + c * 8;
        cpasync16(sptr(As + r * TBK + ((c ^ (r & 7)) << 3)), g);
    }
    if (!TB) {
#pragma unroll
        for (int i = 0; i < 4; i++) {
            int lin = tid + i * 256;
            int r = lin >> 3, c = lin & 7;
            const __nv_bfloat16* g = B + (long)(col0 + r) * ldb + kt * TBK + c * 8;
            cpasync16(sptr(Bs + r * TBK + ((c ^ (r & 7)) << 3)), g);
        }
    } else {
#pragma unroll
        for (int i = 0; i < 4; i++) {
            int lin = tid + i * 256;
            int r = lin >> 4, c = lin & 15;
            const __nv_bfloat16* g = B + (long)(kt * TBK + r) * ldb + col0 + c * 8;
            cpasync16(sptr(Bs + r * TBN + ((c ^ (r & 7)) << 3)), g);
        }
    }
}

// ---------------------------------------------------------------------------
// Core bf16 tensor-core GEMM body (single-barrier 3-stage pipeline).
// MODE 0: bf16 C = acc + bias[col]                     (Q/K/VW projections)
// MODE 1: bf16 C = exp(acc*scale) diag-masked; row sums atomically added to
//         rowsum (= bias ptr, non-const)               (fused scores+exp)
// MODE 2: bf16 C = acc                                 (Wvo weight combine)
// MODE 4: fp32 C = X + beta[0]*(acc/rs[row] + bias[col])  (final fused)
// ---------------------------------------------------------------------------
template<int MODE, bool TB>
__device__ __forceinline__ void gemm_body(
    const __nv_bfloat16* __restrict__ A, const __nv_bfloat16* __restrict__ B,
    const float* __restrict__ bias, void* __restrict__ Cv,
    int K, int lda, int ldb, int ldc,
    const float* __restrict__ X, const float* __restrict__ beta,
    const float* __restrict__ rs2,
    char* dsm, int row0, int col0)
{
    __nv_bfloat16* As = reinterpret_cast<__nv_bfloat16*>(dsm);
    __nv_bfloat16* Bs = As + NSTAGE * STAGE_ELEMS;

    const int tid  = threadIdx.x;
    const int lane = tid & 31;
    const int wid  = tid >> 5;
    const int wm   = (wid & 1) * 64;
    const int wn   = (wid >> 1) * 32;

    float acc[4][4][4];
#pragma unroll
    for (int i = 0; i < 4; i++)
#pragma unroll
        for (int j = 0; j < 4; j++)
#pragma unroll
            for (int k = 0; k < 4; k++) acc[i][j][k] = 0.f;

    const int ntiles = K / TBK;

    GRID_DEP_SYNC();

    issue_tile<TB>(A, B, As, Bs, row0, col0, lda, ldb, 0, tid);
    cp_commit();
    issue_tile<TB>(A, B, As + STAGE_ELEMS, Bs + STAGE_ELEMS, row0, col0, lda, ldb, 1, tid);
    cp_commit();

    for (int kt = 0; kt < ntiles; kt++) {
        const int stg = kt % NSTAGE;
        cp_wait1();
        __syncthreads();

        if (kt + 2 < ntiles) {
            const int ps = (kt + 2) % NSTAGE;
            issue_tile<TB>(A, B, As + ps * STAGE_ELEMS, Bs + ps * STAGE_ELEMS,
                           row0, col0, lda, ldb, kt + 2, tid);
        }
        cp_commit();

        const __nv_bfloat16* Asb = As + stg * STAGE_ELEMS;
        const __nv_bfloat16* Bsb = Bs + stg * STAGE_ELEMS;

#pragma unroll
        for (int ks = 0; ks < 4; ks++) {
            unsigned aF[4][4], bF[4][2];
#pragma unroll
            for (int mi = 0; mi < 4; mi++) {
                int r = wm + mi * 16 + (lane & 15);
                int c = ks * 2 + (lane >> 4);
                ldsm4(aF[mi][0], aF[mi][1], aF[mi][2], aF[mi][3],
                      sptr(Asb + r * TBK + ((c ^ (r & 7)) << 3)));
            }
            if (!TB) {
#pragma unroll
                for (int nt = 0; nt < 2; nt++) {
                    int r = wn + nt * 16 + (lane & 15);
                    int c = ks * 2 + (lane >> 4);
                    unsigned r0, r1, r2, r3;
                    ldsm4(r0, r1, r2, r3,
                          sptr(Bsb + r * TBK + ((c ^ (r & 7)) << 3)));
                    bF[nt * 2 + 0][0] = r0; bF[nt * 2 + 0][1] = r2;
                    bF[nt * 2 + 1][0] = r1; bF[nt * 2 + 1][1] = r3;
                }
            } else {
#pragma unroll
                for (int nt = 0; nt < 2; nt++) {
                    int r = ks * 16 + (lane & 15);
                    int c = (wn >> 3) + nt * 2 + (lane >> 4);
                    unsigned r0, r1, r2, r3;
                    ldsm4t(r0, r1, r2, r3,
                           sptr(Bsb + r * TBN + ((c ^ (r & 7)) << 3)));
                    bF[nt * 2 + 0][0] = r0; bF[nt * 2 + 0][1] = r1;
                    bF[nt * 2 + 1][0] = r2; bF[nt * 2 + 1][1] = r3;
                }
            }
#pragma unroll
            for (int mi = 0; mi < 4; mi++)
#pragma unroll
                for (int nj = 0; nj < 4; nj++)
                    mma16816(acc[mi][nj], aF[mi], bF[nj]);
        }
    }

    // ---------------- epilogue ----------------
    const int rg = lane >> 2;
    const int t  = lane & 3;
    float betav = 0.f;
    if (MODE == 4) betav = beta[0];

    float rsum[4][2];
    if (MODE == 1) {
#pragma unroll
        for (int i = 0; i < 4; i++) { rsum[i][0] = 0.f; rsum[i][1] = 0.f; }
    }

#pragma unroll
    for (int mi = 0; mi < 4; mi++) {
        float inv0 = 0.f, inv1 = 0.f;
        if (MODE == 4) {
            const int r = row0 + wm + mi * 16 + rg;
            inv0 = 1.f / rs2[r];
            inv1 = 1.f / rs2[r + 8];
        }
#pragma unroll
        for (int nj = 0; nj < 4; nj++) {
            const int r = row0 + wm + mi * 16 + rg;
            const int c = col0 + wn + nj * 8 + t * 2;
            const float d0 = acc[mi][nj][0];
            const float d1 = acc[mi][nj][1];
            const float d2 = acc[mi][nj][2];
            const float d3 = acc[mi][nj][3];

            if (MODE == 0) {
                __nv_bfloat16* C = reinterpret_cast<__nv_bfloat16*>(Cv);
                const float2 bb = *reinterpret_cast<const float2*>(bias + c);
                *reinterpret_cast<__nv_bfloat162*>(C + (long)r * ldc + c) =
                    __floats2bfloat162_rn(d0 + bb.x, d1 + bb.y);
                *reinterpret_cast<__nv_bfloat162*>(C + (long)(r + 8) * ldc + c) =
                    __floats2bfloat162_rn(d2 + bb.x, d3 + bb.y);
            } else if (MODE == 1) {
                __nv_bfloat16* C = reinterpret_cast<__nv_bfloat16*>(Cv);
                float e0 = (r     == c    ) ? 0.f : __expf(d0 * SCALE_CONST);
                float e1 = (r     == c + 1) ? 0.f : __expf(d1 * SCALE_CONST);
                float e2 = (r + 8 == c    ) ? 0.f : __expf(d2 * SCALE_CONST);
                float e3 = (r + 8 == c + 1) ? 0.f : __expf(d3 * SCALE_CONST);
                *reinterpret_cast<__nv_bfloat162*>(C + (long)r * ldc + c) =
                    __floats2bfloat162_rn(e0, e1);
                *reinterpret_cast<__nv_bfloat162*>(C + (long)(r + 8) * ldc + c) =
                    __floats2bfloat162_rn(e2, e3);
                rsum[mi][0] += e0 + e1;
                rsum[mi][1] += e2 + e3;
            } else if (MODE == 2) {
                __nv_bfloat16* C = reinterpret_cast<__nv_bfloat16*>(Cv);
                *reinterpret_cast<__nv_bfloat162*>(C + (long)r * ldc + c) =
                    __floats2bfloat162_rn(d0, d1);
                *reinterpret_cast<__nv_bfloat162*>(C + (long)(r + 8) * ldc + c) =
                    __floats2bfloat162_rn(d2, d3);
            } else {  // MODE 4
                float* C = reinterpret_cast<float*>(Cv);
                const float2 bb = *reinterpret_cast<const float2*>(bias + c);
                const float2 x0 = *reinterpret_cast<const float2*>(X + (long)r * ldc + c);
                const float2 x1 = *reinterpret_cast<const float2*>(X + (long)(r + 8) * ldc + c);
                *reinterpret_cast<float2*>(C + (long)r * ldc + c) =
                    make_float2(x0.x + betav * (d0 * inv0 + bb.x),
                                x0.y + betav * (d1 * inv0 + bb.y));
                *reinterpret_cast<float2*>(C + (long)(r + 8) * ldc + c) =
                    make_float2(x1.x + betav * (d2 * inv1 + bb.x),
                                x1.y + betav * (d3 * inv1 + bb.y));
            }
        }
    }

    if (MODE == 1) {
        float* rw = const_cast<float*>(bias);
#pragma unroll
        for (int mi = 0; mi < 4; mi++) {
            float s0 = rsum[mi][0], s1 = rsum[mi][1];
            s0 += __shfl_xor_sync(0xffffffffu, s0, 1);
            s0 += __shfl_xor_sync(0xffffffffu, s0, 2);
            s1 += __shfl_xor_sync(0xffffffffu, s1, 1);
            s1 += __shfl_xor_sync(0xffffffffu, s1, 2);
            if (t == 0) {
                const int r = row0 + wm + mi * 16 + rg;
                atomicAdd(rw + r, s0);
                atomicAdd(rw + r + 8, s1);
            }
        }
    }
}

// ---------------- QKV fused: grid.z in {0,1,2} = Q, K, VW ----------------
__global__ __launch_bounds__(256, 2)
void hgemm_qkv(const __nv_bfloat16* __restrict__ A,
               const __nv_bfloat16* __restrict__ W0, const __nv_bfloat16* __restrict__ W1,
               const __nv_bfloat16* __restrict__ W2,
               const float* __restrict__ b0, const float* __restrict__ b1,
               const float* __restrict__ b2,
               __nv_bfloat16* __restrict__ C0, __nv_bfloat16* __restrict__ C1,
               __nv_bfloat16* __restrict__ C2)
{
    extern __shared__ char dsm[];
    const int z = blockIdx.z;
    const __nv_bfloat16* W = (z == 0) ? W0 : (z == 1) ? W1 : W2;
    const float* bias      = (z == 0) ? b0 : (z == 1) ? b1 : b2;
    __nv_bfloat16* C       = (z == 0) ? C0 : (z == 1) ? C1 : C2;
    gemm_body<0, false>(A, W, bias, C, DIM, DIM, DIM, DIM, nullptr, nullptr, nullptr,
                        dsm, blockIdx.y * TBM, blockIdx.x * TBN);
}

// ---------------- generic batched GEMM (z = group) ----------------
template<int MODE, bool TB>
__global__ __launch_bounds__(256, 2)
void hgemm(const __nv_bfloat16* __restrict__ A, const __nv_bfloat16* __restrict__ B,
           const float* __restrict__ bias, void* __restrict__ Cv,
           int K, int lda, int ldb, int ldc,
           long sA, long sB, long sC,
           const float* __restrict__ X, const float* __restrict__ beta,
           const float* __restrict__ rs)
{
    extern __shared__ char dsm[];
    const int bz = blockIdx.z;
    void* C;
    if (MODE == 4) C = (void*)((float*)Cv + bz * sC);
    else           C = (void*)((__nv_bfloat16*)Cv + bz * sC);
    const float* b  = (MODE == 1) ? bias + (long)bz * GS : bias;
    const float* Xb = (MODE == 4 && X) ? X + bz * sC : X;
    const float* rb = (MODE == 4 && rs) ? rs + (long)bz * GS : rs;
    gemm_body<MODE, TB>(A + bz * sA, B + bz * sB, b, C,
                        K, lda, ldb, ldc, Xb, beta, rb,
                        dsm, blockIdx.y * TBM, blockIdx.x * TBN);
}

// ------- merged fp32->bf16 converts + rowsum zero + bvo = Wo@bv (warp/row) -------
__global__ __launch_bounds__(256)
void conv_all(const float* __restrict__ x,
              const float* __restrict__ wq, const float* __restrict__ wk,
              const float* __restrict__ wv, const float* __restrict__ wo,
              const float* __restrict__ bv,
              __nv_bfloat16* __restrict__ xb,
              __nv_bfloat16* __restrict__ wqb, __nv_bfloat16* __restrict__ wkb,
              __nv_bfloat16* __restrict__ wvb, __nv_bfloat16* __restrict__ wob,
              float* __restrict__ rowsum, float* __restrict__ bvo)
{
    GRID_DEP_SYNC();
    long gid = (long)blockIdx.x * 256 + threadIdx.x;
    if (gid < NG) rowsum[gid] = 0.f;

    // bvo[j] = Wo[j,:] . bv   (one warp per row, first 768 warps)
    long wg = gid >> 5;
    if (wg < DIM) {
        const int lane = threadIdx.x & 31;
        float s = 0.f;
        for (int d = lane; d < DIM; d += 32) s += wo[wg * DIM + d] * bv[d];
#pragma unroll
        for (int o = 16; o; o >>= 1) s += __shfl_xor_sync(0xffffffffu, s, o);
        if (lane == 0) bvo[wg] = s;
    }

    const long NX = (long)NG * DIM;
    const long W  = (long)DIM * DIM;
    long i = gid * 4;
    if (i >= NX + 4 * W) return;
    const float* src;
    __nv_bfloat16* dst;
    long off;
    if (i < NX) { src = x; dst = xb; off = i; }
    else {
        long j = i - NX;
        int w = (int)(j / W);
        off = j - (long)w * W;
        src = (w == 0) ? wq : (w == 1) ? wk : (w == 2) ? wv : wo;
        dst = (w == 0) ? wqb : (w == 1) ? wkb : (w == 2) ? wvb : wob;
    }
    float4 v = *reinterpret_cast<const float4*>(src + off);
    *reinterpret_cast<__nv_bfloat162*>(dst + off)     = __floats2bfloat162_rn(v.x, v.y);
    *reinterpret_cast<__nv_bfloat162*>(dst + off + 2) = __floats2bfloat162_rn(v.z, v.w);
}

// ---------------------------------------------------------------------------
// Launcher. 5 PDL-linked kernels:
//   conv(+bvo) -> Wvo=Wo@Wv -> QKV'(Q,K,VW) -> scores(exp+rowsum) -> final
// final: out = x + beta*((P@VW)/rs + bo)
// ---------------------------------------------------------------------------
extern "C" void kernel_launch(void* const* d_in, const int* in_sizes, int n_in,
                              void* d_out, int out_size)
{
    (void)in_sizes; (void)n_in; (void)out_size;
    const float* x    = (const float*)d_in[0];
    const float* Wq   = (const float*)d_in[2];
    const float* bq   = (const float*)d_in[3];
    const float* Wk   = (const float*)d_in[4];
    const float* bk   = (const float*)d_in[5];
    const float* Wv   = (const float*)d_in[6];
    const float* bv   = (const float*)d_in[7];
    const float* Wo   = (const float*)d_in[8];
    const float* bo   = (const float*)d_in[9];
    const float* beta = (const float*)d_in[10];
    float* out = (float*)d_out;

    __nv_bfloat16 *xb, *Wqb, *Wkb, *Wvb, *Wob, *Wvo, *Q, *K, *VW, *P;
    float *RS, *BVO;
    cudaGetSymbolAddress((void**)&xb,  g_xb);
    cudaGetSymbolAddress((void**)&Wqb, g_Wqb);
    cudaGetSymbolAddress((void**)&Wkb, g_Wkb);
    cudaGetSymbolAddress((void**)&Wvb, g_Wvb);
    cudaGetSymbolAddress((void**)&Wob, g_Wob);
    cudaGetSymbolAddress((void**)&Wvo, g_Wvo);
    cudaGetSymbolAddress((void**)&Q,   g_Q);
    cudaGetSymbolAddress((void**)&K,   g_K);
    cudaGetSymbolAddress((void**)&VW,  g_VW);
    cudaGetSymbolAddress((void**)&P,   g_P);
    cudaGetSymbolAddress((void**)&RS,  g_rs);
    cudaGetSymbolAddress((void**)&BVO, g_bvo);

    static bool init_done = false;
    if (!init_done) {
        cudaFuncSetAttribute(hgemm_qkv,       cudaFuncAttributeMaxDynamicSharedMemorySize, SMEM_BYTES);
        cudaFuncSetAttribute(hgemm<1, false>, cudaFuncAttributeMaxDynamicSharedMemorySize, SMEM_BYTES);
        cudaFuncSetAttribute(hgemm<2, true>,  cudaFuncAttributeMaxDynamicSharedMemorySize, SMEM_BYTES);
        cudaFuncSetAttribute(hgemm<4, true>,  cudaFuncAttributeMaxDynamicSharedMemorySize, SMEM_BYTES);
        init_done = true;
    }

    cudaLaunchAttribute pdl[1];
    pdl[0].id = cudaLaunchAttributeProgrammaticStreamSerialization;
    pdl[0].val.programmaticStreamSerializationAllowed = 1;

    auto mkcfg = [&](dim3 g, dim3 b, size_t sm) {
        cudaLaunchConfig_t cfg{};
        cfg.gridDim = g;
        cfg.blockDim = b;
        cfg.dynamicSmemBytes = sm;
        cfg.stream = 0;
        cfg.attrs = pdl;
        cfg.numAttrs = 1;
        return cfg;
    };

    // converts + rowsum zero + bvo
    {
        long total4 = ((long)NG * DIM + 4L * DIM * DIM) / 4;
        int blocks = (int)((total4 + 255) / 256);
        cudaLaunchConfig_t cfg = mkcfg(dim3(blocks), dim3(256), 0);
        cudaLaunchKernelEx(&cfg, conv_all, x, Wq, Wk, Wv, Wo, bv,
                           xb, Wqb, Wkb, Wvb, Wob, RS, BVO);
    }

    // Wvo = Wo @ Wv  (NN via TB=true: A=Wo [j,d], B=Wv [d,e]) -> bf16
    {
        cudaLaunchConfig_t cfg = mkcfg(dim3(6, 6, 1), dim3(256), SMEM_BYTES);
        cudaLaunchKernelEx(&cfg, hgemm<2, true>,
                           (const __nv_bfloat16*)Wob, (const __nv_bfloat16*)Wvb,
                           (const float*)nullptr, (void*)Wvo,
                           DIM, DIM, DIM, DIM, 0L, 0L, 0L,
                           (const float*)nullptr, (const float*)nullptr,
                           (const float*)nullptr);
    }

    // Q, K, VW projections in one launch (VW = x@Wvo^T + bvo)
    {
        cudaLaunchConfig_t cfg = mkcfg(dim3(6, 64, 3), dim3(256), SMEM_BYTES);
        cudaLaunchKernelEx(&cfg, hgemm_qkv, (const __nv_bfloat16*)xb,
                           (const __nv_bfloat16*)Wqb, (const __nv_bfloat16*)Wkb,
                           (const __nv_bfloat16*)Wvo, bq, bk, (const float*)BVO,
                           Q, K, VW);
    }

    // fused scores+exp+rowsum: P_g = exp(scale * Q_g K_g^T) masked, bf16
    {
        cudaLaunchConfig_t cfg = mkcfg(dim3(4, 4, BGRP), dim3(256), SMEM_BYTES);
        cudaLaunchKernelEx(&cfg, hgemm<1, false>,
                           (const __nv_bfloat16*)Q, (const __nv_bfloat16*)K,
                           (const float*)RS, (void*)P,
                           DIM, DIM, DIM, GS,
                           (long)GS * DIM, (long)GS * DIM, (long)GS * GS,
                           (const float*)nullptr, (const float*)nullptr,
                           (const float*)nullptr);
    }

    // final: out = x + beta*((P_g @ VW_g)/rs + bo)  (batched z=16, fp32)
    {
        cudaLaunchConfig_t cfg = mkcfg(dim3(6, 4, BGRP), dim3(256), SMEM_BYTES);
        cudaLaunchKernelEx(&cfg, hgemm<4, true>,
                           (const __nv_bfloat16*)P, (const __nv_bfloat16*)VW,
                           bo, (void*)out,
                           GS, GS, DIM, DIM,
                           (long)GS * GS, (long)GS * DIM, (long)GS * DIM,
                           x, beta, (const float*)RS);
    }
}